// round 1
// baseline (speedup 1.0000x reference)
#include <cuda_runtime.h>
#include <math.h>

#define Bb 8
#define Cc 128
#define Nn 65536
#define Ll 64

// Accumulators in device globals (no allocation allowed).
__device__ float g_centers[Bb * Ll * Cc];   // unnormalized sums, fully overwritten each call
__device__ float g_vsum[Bb * Ll];           // atomically accumulated -> zeroed by k0
__device__ float g_cnt[Bb * Ll];            // atomically accumulated -> zeroed by k0

// ---------------------------------------------------------------------------
// K0: zero the atomic accumulators and the output.
// ---------------------------------------------------------------------------
__global__ void k0_zero(float* out, int out_size) {
    int t = blockIdx.x * blockDim.x + threadIdx.x;
    int stride = gridDim.x * blockDim.x;
    for (int i = t; i < Bb * Ll; i += stride) { g_vsum[i] = 0.0f; g_cnt[i] = 0.0f; }
    for (int i = t; i < out_size; i += stride) out[i] = 0.0f;
}

// ---------------------------------------------------------------------------
// K1: per-point pass. Thread owns one point; loops over all 128 channels
// (coalesced along n). Computes v = relu(||x - mean||-0.5)^2 and scatters
// v and 1.0 into per-label sums (one shared atomic per point).
// ---------------------------------------------------------------------------
__global__ __launch_bounds__(256) void k1_points(const float* __restrict__ pred,
                                                 const int* __restrict__ label) {
    const int b = blockIdx.y;
    const int n = blockIdx.x * 256 + threadIdx.x;

    const float* p = pred + (size_t)b * Cc * Nn + n;
    float s1 = 0.0f, s2 = 0.0f;
#pragma unroll 8
    for (int c = 0; c < Cc; c++) {
        float x = p[(size_t)c * Nn];
        s1 += x;
        s2 = fmaf(x, x, s2);
    }
    float pn2 = s2 - s1 * s1 * (1.0f / Cc);
    pn2 = fmaxf(pn2, 0.0f);
    float d = sqrtf(pn2) - 0.5f;            // D_VAR = 0.5
    float v = (d > 0.0f) ? d * d : 0.0f;

    int lab = label[b * Nn + n];

    __shared__ float vs[Ll];
    __shared__ float cs[Ll];
    if (threadIdx.x < Ll) { vs[threadIdx.x] = 0.0f; cs[threadIdx.x] = 0.0f; }
    __syncthreads();
    atomicAdd(&vs[lab], v);
    atomicAdd(&cs[lab], 1.0f);
    __syncthreads();
    if (threadIdx.x < Ll) {
        atomicAdd(&g_vsum[b * Ll + threadIdx.x], vs[threadIdx.x]);
        atomicAdd(&g_cnt[b * Ll + threadIdx.x], cs[threadIdx.x]);
    }
}

// ---------------------------------------------------------------------------
// K2: centers pass. One block per (b, c). 128 threads; thread t owns SMEM
// column acc[*][t] -> label-bucketed accumulation with NO atomics.
// Row stride 129 keeps lanes on distinct banks (bank = (lab+t)%32).
// Each (b,c) handled by exactly one block -> direct store, no global atomics.
// ---------------------------------------------------------------------------
__global__ __launch_bounds__(128) void k2_centers(const float* __restrict__ pred,
                                                  const int* __restrict__ label) {
    const int c = blockIdx.x;
    const int b = blockIdx.y;
    const int tid = threadIdx.x;   // 0..127

    __shared__ float acc[Ll][129];
    for (int i = tid; i < Ll * 129; i += 128) ((float*)acc)[i] = 0.0f;
    __syncthreads();

    const float4* p4 = (const float4*)(pred + (size_t)b * Cc * Nn + (size_t)c * Nn);
    const int4*   l4 = (const int4*)(label + b * Nn);

#pragma unroll 2
    for (int i = 0; i < Nn / (128 * 4); i++) {   // 128 iterations
        int idx = i * 128 + tid;
        float4 x = p4[idx];
        int4 lb = l4[idx];
        acc[lb.x][tid] += x.x;
        acc[lb.y][tid] += x.y;
        acc[lb.z][tid] += x.z;
        acc[lb.w][tid] += x.w;
    }
    __syncthreads();

    if (tid < Ll) {
        float s = 0.0f;
#pragma unroll 8
        for (int j = 0; j < 128; j++) s += acc[tid][j];
        g_centers[((size_t)b * Ll + tid) * Cc + c] = s;
    }
}

// ---------------------------------------------------------------------------
// K3: finalize. grid (4, B): block (q,b) handles d in [q*32,(q+1)*32).
// Loads centers (normalized by counts) into SMEM, computes sqn, then the
// pairwise hinge term; q==0 also adds the reg and var terms.
// ---------------------------------------------------------------------------
__global__ __launch_bounds__(256) void k3_final(float* __restrict__ out) {
    const int b = blockIdx.y;
    const int q = blockIdx.x;       // 0..3
    const int tid = threadIdx.x;    // 0..255

    __shared__ float cen[Ll][Cc];   // 32 KB
    __shared__ float sqn[Cc];
    __shared__ float red[8];

    for (int i = tid; i < Ll * Cc; i += 256) {
        int l = i >> 7;
        cen[l][i & 127] = g_centers[(size_t)b * Ll * Cc + i] / g_cnt[b * Ll + l];
    }
    __syncthreads();

    if (tid < Cc) {
        float s = 0.0f;
#pragma unroll 8
        for (int l = 0; l < Ll; l++) { float v = cen[l][tid]; s = fmaf(v, v, s); }
        sqn[tid] = s;
    }
    __syncthreads();

    float local = 0.0f;
#pragma unroll 1
    for (int t = 0; t < 16; t++) {
        int p = t * 256 + tid;            // 0..4095
        int cc = p & 127;
        int d  = q * 32 + (p >> 7);
        float g = 0.0f;
#pragma unroll 8
        for (int l = 0; l < Ll; l++) g = fmaf(cen[l][cc], cen[l][d], g);
        float sqd = fmaxf(sqn[cc] + sqn[d] - 2.0f * g, 0.0f);
        float dist = (sqd > 0.0f) ? sqrtf(sqd) : 0.0f;
        float h = fmaxf(3.0f - dist, 0.0f);   // 2*D_DIST = 3.0
        local = fmaf(h, h, local);
    }
    // P_DIST / (2*L*(L-1+1e-16)) = 1/8064
    local *= (1.0f / 8064.0f);

    if (q == 0) {
        if (tid < Cc) local += 0.001f * sqrtf(sqn[tid]) * (1.0f / 64.0f);         // l_reg term
        if (tid < Ll) local += g_vsum[b * Ll + tid] / g_cnt[b * Ll + tid] * (1.0f / 64.0f); // var term
    }

    // block reduction
    for (int off = 16; off > 0; off >>= 1)
        local += __shfl_down_sync(0xFFFFFFFFu, local, off);
    if ((tid & 31) == 0) red[tid >> 5] = local;
    __syncthreads();
    if (tid == 0) {
        float s = 0.0f;
#pragma unroll
        for (int w = 0; w < 8; w++) s += red[w];
        atomicAdd(out, s);
    }
}

// ---------------------------------------------------------------------------
extern "C" void kernel_launch(void* const* d_in, const int* in_sizes, int n_in,
                              void* d_out, int out_size) {
    const float* pred  = (const float*)d_in[0];
    const int*   label = (const int*)d_in[1];
    float* out = (float*)d_out;

    k0_zero<<<4, 256>>>(out, out_size);
    k1_points<<<dim3(Nn / 256, Bb), 256>>>(pred, label);
    k2_centers<<<dim3(Cc, Bb), 128>>>(pred, label);
    k3_final<<<dim3(4, Bb), 256>>>(out);
}